// round 3
// baseline (speedup 1.0000x reference)
#include <cuda_runtime.h>
#include <cstdint>

#define T_LEN 16384
#define DIM   300
#define UU    300
#define G4    1200
#define KP    320      // padded h-row width (300 real + 20 zero pad)
#define AD    350
#define RR    30

#define REC_NCTA 60    // CTAs per direction
#define REC_OUT  5     // h outputs per CTA (warp each)
#define REC_THREADS 160

// ---------------- static scratch (no allocations allowed) ----------------
__device__ __align__(128) float g_Hf[(T_LEN + 1) * KP];   // row t+1 = h_f[t], row 0 zeros
__device__ __align__(128) float g_Hb[(T_LEN + 1) * KP];   // row t   = h_b[t], row T zeros
__device__ __align__(128) float g_xpf[(size_t)T_LEN * G4];
__device__ __align__(128) float g_xpb[(size_t)T_LEN * G4];
__device__ __align__(128) float g_W1T[600 * AD];          // W1T[u][a] = W1[a][u]
__device__ __align__(128) float g_T1[(size_t)T_LEN * AD]; // tanh(W1 @ H^T)^T : [t][a]
__device__ __align__(128) float g_S2[(size_t)RR * T_LEN]; // [r][t]
__device__ __align__(128) float g_p[T_LEN];
__device__ __align__(128) float g_sr[RR];

// ---------------- helpers ----------------
__device__ __forceinline__ float ldvf(const float* p) {
    float v;
    asm volatile("ld.volatile.global.f32 %0, [%1];" : "=f"(v) : "l"(p));
    return v;
}
__device__ __forceinline__ void stvf(float* p, float v) {
    asm volatile("st.volatile.global.f32 [%0], %1;" :: "l"(p), "f"(v) : "memory");
}
__device__ __forceinline__ float fsig(float x) {
    return 1.0f / (1.0f + __expf(-x));
}

// ---------------- init: poison H rows, zero boundary rows, transpose W1 ------
__global__ void k_init(const float* __restrict__ W1) {
    long stride = (long)gridDim.x * blockDim.x;
    long i0 = (long)blockIdx.x * blockDim.x + threadIdx.x;
    long total = (long)(T_LEN + 1) * KP;
    for (long idx = i0; idx < total; idx += stride) {
        long row = idx / KP;
        int  col = (int)(idx % KP);
        unsigned pf = (row == 0)     ? 0u : (col < UU ? 0xFFFFFFFFu : 0u);
        unsigned pb = (row == T_LEN) ? 0u : (col < UU ? 0xFFFFFFFFu : 0u);
        reinterpret_cast<unsigned*>(g_Hf)[idx] = pf;
        reinterpret_cast<unsigned*>(g_Hb)[idx] = pb;
    }
    for (long idx = i0; idx < (long)600 * AD; idx += stride) {
        int u = (int)(idx / AD), a = (int)(idx % AD);
        g_W1T[idx] = W1[a * 600 + u];
    }
}

// ---------------- xp = x @ Wk + b  (both directions via blockIdx.z) ---------
__global__ __launch_bounds__(256) void k_xp(
    const float* __restrict__ x,
    const float* __restrict__ Wf, const float* __restrict__ bf,
    const float* __restrict__ Wb, const float* __restrict__ bb)
{
    const float* W    = blockIdx.z ? Wb : Wf;
    const float* bias = blockIdx.z ? bb : bf;
    float*       C    = blockIdx.z ? g_xpb : g_xpf;

    int m0 = blockIdx.y * 64, n0 = blockIdx.x * 64;
    __shared__ float As[20][64];
    __shared__ float Bs[20][64];
    int tid = threadIdx.x;
    int tx = tid & 15, ty = tid >> 4;

    float acc[4][4];
#pragma unroll
    for (int i = 0; i < 4; i++)
#pragma unroll
        for (int j = 0; j < 4; j++) acc[i][j] = 0.f;

    for (int k0 = 0; k0 < DIM; k0 += 20) {
        for (int i = tid; i < 64 * 20; i += 256) {
            int m = i / 20, kk = i % 20;
            As[kk][m] = x[(size_t)(m0 + m) * DIM + k0 + kk];
        }
        for (int i = tid; i < 20 * 64; i += 256) {
            int kk = i / 64, n = i % 64;
            int nn = n0 + n;
            Bs[kk][n] = (nn < G4) ? W[(size_t)(k0 + kk) * G4 + nn] : 0.f;
        }
        __syncthreads();
#pragma unroll
        for (int kk = 0; kk < 20; kk++) {
            float a[4], b[4];
#pragma unroll
            for (int i = 0; i < 4; i++) a[i] = As[kk][ty * 4 + i];
#pragma unroll
            for (int j = 0; j < 4; j++) b[j] = Bs[kk][tx * 4 + j];
#pragma unroll
            for (int i = 0; i < 4; i++)
#pragma unroll
                for (int j = 0; j < 4; j++) acc[i][j] = fmaf(a[i], b[j], acc[i][j]);
        }
        __syncthreads();
    }
#pragma unroll
    for (int i = 0; i < 4; i++)
#pragma unroll
        for (int j = 0; j < 4; j++) {
            int n = n0 + tx * 4 + j;
            if (n < G4)
                C[(size_t)(m0 + ty * 4 + i) * G4 + n] = acc[i][j] + bias[n];
        }
}

// ---------------- recurrence: 120 persistent CTAs, data-as-flag dataflow ----
// xp stream is software-pipelined one step ahead so its DRAM latency hides
// under the (poll + gate math) of the previous step.
__global__ __launch_bounds__(REC_THREADS, 1) void k_rec(
    const float* __restrict__ Wrf, const float* __restrict__ Wrb)
{
    int b    = blockIdx.x;
    int dir  = (b >= REC_NCTA) ? 1 : 0;
    int cidx = dir ? (b - REC_NCTA) : b;
    const float* Wr = dir ? Wrb : Wrf;
    const float* xp = dir ? g_xpb : g_xpf;
    float*       Hd = dir ? g_Hb : g_Hf;

    int tid  = threadIdx.x;
    int wid  = tid >> 5, lane = tid & 31;
    int u    = cidx * REC_OUT + wid;           // output unit 0..299

    // register-resident recurrent weights: w[g][k] = Wr[v][g*300+u], v = lane+32k
    float w[4][10];
#pragma unroll
    for (int g = 0; g < 4; g++)
#pragma unroll
        for (int k = 0; k < 10; k++) {
            int v = lane + 32 * k;
            w[g][k] = (v < UU) ? Wr[(size_t)v * G4 + g * UU + u] : 0.f;
        }

    // prefetch xp for step s=0
    float xn0 = 0.f, xn1 = 0.f, xn2 = 0.f, xn3 = 0.f;
    if (lane == 0) {
        int t0 = dir ? (T_LEN - 1) : 0;
        const float* xr = xp + (size_t)t0 * G4 + u;
        xn0 = __ldcg(xr);
        xn1 = __ldcg(xr + UU);
        xn2 = __ldcg(xr + 2 * UU);
        xn3 = __ldcg(xr + 3 * UU);
    }

    float c = 0.f;
    for (int s = 0; s < T_LEN; s++) {
        int  t    = dir ? (T_LEN - 1 - s) : s;
        long rrow = dir ? (long)(t + 1) * KP : (long)t * KP;       // h_prev row
        long wrow = dir ? (long)t * KP       : (long)(t + 1) * KP; // h_out row

        // consume prefetched xp, then issue prefetch for step s+1 (full step
        // of latency slack before its use)
        float x0 = xn0, x1 = xn1, x2 = xn2, x3 = xn3;
        if (lane == 0 && s + 1 < T_LEN) {
            int tn = dir ? (t - 1) : (t + 1);
            const float* xr = xp + (size_t)tn * G4 + u;
            xn0 = __ldcg(xr);
            xn1 = __ldcg(xr + UU);
            xn2 = __ldcg(xr + 2 * UU);
            xn3 = __ldcg(xr + 3 * UU);
        }

        // poll previous h row; valid h has float bits < 0x40000000 (h in [0,1)),
        // poison is 0xFFFFFFFF
        float hv[10];
        bool ok;
        do {
            ok = true;
#pragma unroll
            for (int k = 0; k < 10; k++) {
                hv[k] = ldvf(&Hd[rrow + lane + 32 * k]);
                ok &= (__float_as_uint(hv[k]) < 0x40000000u);
            }
        } while (!__all_sync(0xffffffffu, ok));

        // four gate dot-products
        float a0 = 0.f, a1 = 0.f, a2 = 0.f, a3 = 0.f;
#pragma unroll
        for (int k = 0; k < 10; k++) {
            a0 = fmaf(hv[k], w[0][k], a0);
            a1 = fmaf(hv[k], w[1][k], a1);
            a2 = fmaf(hv[k], w[2][k], a2);
            a3 = fmaf(hv[k], w[3][k], a3);
        }
#pragma unroll
        for (int off = 16; off > 0; off >>= 1) {
            a0 += __shfl_xor_sync(0xffffffffu, a0, off);
            a1 += __shfl_xor_sync(0xffffffffu, a1, off);
            a2 += __shfl_xor_sync(0xffffffffu, a2, off);
            a3 += __shfl_xor_sync(0xffffffffu, a3, off);
        }

        if (lane == 0) {
            float zi = fsig(x0 + a0);
            float zf = fsig(x1 + a1);
            float zg = fsig(x2 + a2);
            float zo = fsig(x3 + a3);
            c = fmaf(zf, c, zi * zg);
            float h = zo * fsig(c);
            stvf(&Hd[wrow + u], h);
        }
    }
}

// ---------------- T1[t][a] = tanh( sum_u H[t][u] * W1T[u][a] ) --------------
__global__ __launch_bounds__(256) void k_t1() {
    int a0 = blockIdx.x * 64, t0 = blockIdx.y * 64;
    __shared__ float As[20][64];  // H chunk
    __shared__ float Bs[20][64];  // W1T chunk
    int tid = threadIdx.x;
    int tx = tid & 15, ty = tid >> 4;

    float acc[4][4];
#pragma unroll
    for (int i = 0; i < 4; i++)
#pragma unroll
        for (int j = 0; j < 4; j++) acc[i][j] = 0.f;

    for (int k0 = 0; k0 < 600; k0 += 20) {
        for (int i = tid; i < 64 * 20; i += 256) {
            int m = i / 20, kk = i % 20;
            int uu = k0 + kk;
            float v = (uu < UU) ? g_Hf[(size_t)(t0 + m + 1) * KP + uu]
                                : g_Hb[(size_t)(t0 + m) * KP + (uu - UU)];
            As[kk][m] = v;
        }
        for (int i = tid; i < 20 * 64; i += 256) {
            int kk = i / 64, j = i % 64;
            int a = a0 + j;
            Bs[kk][j] = (a < AD) ? g_W1T[(size_t)(k0 + kk) * AD + a] : 0.f;
        }
        __syncthreads();
#pragma unroll
        for (int kk = 0; kk < 20; kk++) {
            float a[4], b[4];
#pragma unroll
            for (int i = 0; i < 4; i++) a[i] = As[kk][ty * 4 + i];
#pragma unroll
            for (int j = 0; j < 4; j++) b[j] = Bs[kk][tx * 4 + j];
#pragma unroll
            for (int i = 0; i < 4; i++)
#pragma unroll
                for (int j = 0; j < 4; j++) acc[i][j] = fmaf(a[i], b[j], acc[i][j]);
        }
        __syncthreads();
    }
#pragma unroll
    for (int i = 0; i < 4; i++)
#pragma unroll
        for (int j = 0; j < 4; j++) {
            int a = a0 + tx * 4 + j;
            if (a < AD)
                g_T1[(size_t)(t0 + ty * 4 + i) * AD + a] = tanhf(acc[i][j]);
        }
}

// ---------------- p[t] = H[t] . dense_w -------------------------------------
__global__ __launch_bounds__(256) void k_p(const float* __restrict__ dw) {
    int wid = threadIdx.x >> 5, lane = threadIdx.x & 31;
    int t = blockIdx.x * 8 + wid;
    if (t >= T_LEN) return;
    float s = 0.f;
    for (int u = lane; u < 600; u += 32) {
        float h = (u < UU) ? g_Hf[(size_t)(t + 1) * KP + u]
                           : g_Hb[(size_t)t * KP + (u - UU)];
        s = fmaf(h, __ldg(&dw[u]), s);
    }
#pragma unroll
    for (int off = 16; off > 0; off >>= 1) s += __shfl_xor_sync(0xffffffffu, s, off);
    if (lane == 0) g_p[t] = s;
}

// ---------------- S2[r][t] = sum_a W2[r][a] * T1[t][a] ----------------------
__global__ __launch_bounds__(256) void k_s2(const float* __restrict__ W2) {
    __shared__ float Ws[RR * AD];   // 42 KB
    int tid = threadIdx.x;
    for (int i = tid; i < RR * AD; i += 256) Ws[i] = W2[i];
    __syncthreads();

    int wid = tid >> 5, lane = tid & 31;
    int t = blockIdx.x * 8 + wid;
    if (t >= T_LEN) return;

    float tv[11];
#pragma unroll
    for (int k = 0; k < 11; k++) {
        int a = lane + 32 * k;
        tv[k] = (a < AD) ? g_T1[(size_t)t * AD + a] : 0.f;
    }
    for (int r = 0; r < RR; r++) {
        float s = 0.f;
#pragma unroll
        for (int k = 0; k < 11; k++) {
            int a = lane + 32 * k;
            if (a < AD) s = fmaf(tv[k], Ws[r * AD + a], s);
        }
#pragma unroll
        for (int off = 16; off > 0; off >>= 1) s += __shfl_xor_sync(0xffffffffu, s, off);
        if (lane == 0) g_S2[(size_t)r * T_LEN + t] = s;
    }
}

// ---------------- softmax over t + weighted p reduction per r ---------------
__global__ __launch_bounds__(256) void k_soft() {
    int r = blockIdx.x;
    int tid = threadIdx.x;
    const float* row = g_S2 + (size_t)r * T_LEN;
    __shared__ float red[256];
    __shared__ float red2[256];

    float m = -1e30f;
    for (int i = tid; i < T_LEN; i += 256) m = fmaxf(m, row[i]);
    red[tid] = m; __syncthreads();
    for (int s = 128; s > 0; s >>= 1) {
        if (tid < s) red[tid] = fmaxf(red[tid], red[tid + s]);
        __syncthreads();
    }
    m = red[0]; __syncthreads();

    float se = 0.f, sp = 0.f;
    for (int i = tid; i < T_LEN; i += 256) {
        float e = expf(row[i] - m);
        se += e;
        sp = fmaf(e, g_p[i], sp);
    }
    red[tid] = se; red2[tid] = sp; __syncthreads();
    for (int s = 128; s > 0; s >>= 1) {
        if (tid < s) { red[tid] += red[tid + s]; red2[tid] += red2[tid + s]; }
        __syncthreads();
    }
    if (tid == 0) g_sr[r] = red2[0] / red[0];
}

// ---------------- final scalar ----------------------------------------------
__global__ void k_fin(const float* __restrict__ db, float* __restrict__ out) {
    int lane = threadIdx.x;
    float s = (lane < RR) ? g_sr[lane] : 0.f;
#pragma unroll
    for (int off = 16; off > 0; off >>= 1) s += __shfl_xor_sync(0xffffffffu, s, off);
    if (lane == 0)
        out[0] = 1.0f / (1.0f + expf(-(s / (float)RR + db[0])));
}

// ---------------- launch ----------------------------------------------------
extern "C" void kernel_launch(void* const* d_in, const int* in_sizes, int n_in,
                              void* d_out, int out_size) {
    const float* emb  = (const float*)d_in[0];
    const float* Wk_f = (const float*)d_in[1];
    const float* Wr_f = (const float*)d_in[2];
    const float* b_f  = (const float*)d_in[3];
    const float* Wk_b = (const float*)d_in[4];
    const float* Wr_b = (const float*)d_in[5];
    const float* b_b  = (const float*)d_in[6];
    const float* W1   = (const float*)d_in[7];
    const float* W2   = (const float*)d_in[8];
    const float* dw   = (const float*)d_in[9];
    const float* db   = (const float*)d_in[10];
    float* out = (float*)d_out;

    k_init<<<2048, 256>>>(W1);
    k_xp<<<dim3((G4 + 63) / 64, T_LEN / 64, 2), 256>>>(emb, Wk_f, b_f, Wk_b, b_b);
    k_rec<<<2 * REC_NCTA, REC_THREADS>>>(Wr_f, Wr_b);
    k_t1<<<dim3((AD + 63) / 64, T_LEN / 64), 256>>>();
    k_p<<<T_LEN / 8, 256>>>(dw);
    k_s2<<<T_LEN / 8, 256>>>(W2);
    k_soft<<<RR, 256>>>();
    k_fin<<<1, 32>>>(db, out);
}

// round 5
// speedup vs baseline: 3.2363x; 3.2363x over previous
#include <cuda_runtime.h>
#include <cstdint>

#define T_LEN 16384
#define DIM   300
#define UU    300
#define G4    1200
#define KP    320      // padded h-row width (300 real + 20 zero pad); 5 chunks of 64
#define AD    350
#define RR    30

#define REC_NCTA 60    // CTAs per direction
#define REC_OUT  5     // h outputs per CTA (warp each)
#define REC_THREADS 160

// ---------------- static scratch (no allocations allowed) ----------------
__device__ __align__(128) float g_Hf[(T_LEN + 1) * KP];   // row t+1 = h_f[t], row 0 zeros
__device__ __align__(128) float g_Hb[(T_LEN + 1) * KP];   // row t   = h_b[t], row T zeros
__device__ __align__(128) float g_xpf[(size_t)T_LEN * G4];
__device__ __align__(128) float g_xpb[(size_t)T_LEN * G4];
__device__ __align__(128) float g_W1T[600 * AD];          // W1T[u][a] = W1[a][u]
__device__ __align__(128) float g_T1[(size_t)T_LEN * AD]; // tanh(W1 @ H^T)^T : [t][a]
__device__ __align__(128) float g_S2[(size_t)RR * T_LEN]; // [r][t]
__device__ __align__(128) float g_p[T_LEN];
__device__ __align__(128) float g_sr[RR];

// ---------------- helpers ----------------
// Pipelined, L1-bypassing, re-executed vector load for the poll loop.
// Weak .cg (no STRONG semantics) so the 16 lane loads fly in parallel;
// asm volatile + memory clobber forces a fresh load every poll iteration.
__device__ __forceinline__ float4 ldcg4(const float4* p) {
    float4 v;
    asm volatile("ld.global.cg.v4.f32 {%0,%1,%2,%3}, [%4];"
                 : "=f"(v.x), "=f"(v.y), "=f"(v.z), "=f"(v.w)
                 : "l"(p) : "memory");
    return v;
}
// Weak producer store. No ordering needed: the 4B value IS the ready flag
// (valid h bits < 0x40000000, poison 0xFFFFFFFF; 4B aligned access is atomic).
// Avoids the .STRONG.SYS scope promotion a volatile store would carry.
__device__ __forceinline__ void stcg(float* p, float v) {
    asm volatile("st.global.cg.f32 [%0], %1;" :: "l"(p), "f"(v) : "memory");
}
__device__ __forceinline__ float fsig(float x) {
    return 1.0f / (1.0f + __expf(-x));
}

// no-op padding kernels so ncu (-s 5 -c 1) lands on k_rec
__global__ void k_nop() {}

// ---------------- init: poison H rows, zero boundary rows, transpose W1 ------
__global__ void k_init(const float* __restrict__ W1) {
    long stride = (long)gridDim.x * blockDim.x;
    long i0 = (long)blockIdx.x * blockDim.x + threadIdx.x;
    long total = (long)(T_LEN + 1) * KP;
    for (long idx = i0; idx < total; idx += stride) {
        long row = idx / KP;
        int  col = (int)(idx % KP);
        unsigned pf = (row == 0)     ? 0u : (col < UU ? 0xFFFFFFFFu : 0u);
        unsigned pb = (row == T_LEN) ? 0u : (col < UU ? 0xFFFFFFFFu : 0u);
        reinterpret_cast<unsigned*>(g_Hf)[idx] = pf;
        reinterpret_cast<unsigned*>(g_Hb)[idx] = pb;
    }
    for (long idx = i0; idx < (long)600 * AD; idx += stride) {
        int u = (int)(idx / AD), a = (int)(idx % AD);
        g_W1T[idx] = W1[a * 600 + u];
    }
}

// ---------------- xp = x @ Wk + b  (both directions via blockIdx.z) ---------
__global__ __launch_bounds__(256) void k_xp(
    const float* __restrict__ x,
    const float* __restrict__ Wf, const float* __restrict__ bf,
    const float* __restrict__ Wb, const float* __restrict__ bb)
{
    const float* W    = blockIdx.z ? Wb : Wf;
    const float* bias = blockIdx.z ? bb : bf;
    float*       C    = blockIdx.z ? g_xpb : g_xpf;

    int m0 = blockIdx.y * 64, n0 = blockIdx.x * 64;
    __shared__ float As[20][64];
    __shared__ float Bs[20][64];
    int tid = threadIdx.x;
    int tx = tid & 15, ty = tid >> 4;

    float acc[4][4];
#pragma unroll
    for (int i = 0; i < 4; i++)
#pragma unroll
        for (int j = 0; j < 4; j++) acc[i][j] = 0.f;

    for (int k0 = 0; k0 < DIM; k0 += 20) {
        for (int i = tid; i < 64 * 20; i += 256) {
            int m = i / 20, kk = i % 20;
            As[kk][m] = x[(size_t)(m0 + m) * DIM + k0 + kk];
        }
        for (int i = tid; i < 20 * 64; i += 256) {
            int kk = i / 64, n = i % 64;
            int nn = n0 + n;
            Bs[kk][n] = (nn < G4) ? W[(size_t)(k0 + kk) * G4 + nn] : 0.f;
        }
        __syncthreads();
#pragma unroll
        for (int kk = 0; kk < 20; kk++) {
            float a[4], b[4];
#pragma unroll
            for (int i = 0; i < 4; i++) a[i] = As[kk][ty * 4 + i];
#pragma unroll
            for (int j = 0; j < 4; j++) b[j] = Bs[kk][tx * 4 + j];
#pragma unroll
            for (int i = 0; i < 4; i++)
#pragma unroll
                for (int j = 0; j < 4; j++) acc[i][j] = fmaf(a[i], b[j], acc[i][j]);
        }
        __syncthreads();
    }
#pragma unroll
    for (int i = 0; i < 4; i++)
#pragma unroll
        for (int j = 0; j < 4; j++) {
            int n = n0 + tx * 4 + j;
            if (n < G4)
                C[(size_t)(m0 + ty * 4 + i) * G4 + n] = acc[i][j] + bias[n];
        }
}

// ---------------- recurrence: 120 persistent CTAs, data-as-flag dataflow ----
// Each warp polls ONLY its 64-float chunk of the previous h row (one half-warp
// LDG.128 per iteration), stages it into double-buffered smem; after one
// __syncthreads all warps read the full row from smem. Poll L2 traffic /5,
// LSU issue /10 vs the all-warps-poll-everything scheme.
__global__ __launch_bounds__(REC_THREADS, 1) void k_rec(
    const float* __restrict__ Wrf, const float* __restrict__ Wrb)
{
    __shared__ float hbuf[2][KP];

    int b    = blockIdx.x;
    int dir  = (b >= REC_NCTA) ? 1 : 0;
    int cidx = dir ? (b - REC_NCTA) : b;
    const float* Wr = dir ? Wrb : Wrf;
    const float* xp = dir ? g_xpb : g_xpf;
    float*       Hd = dir ? g_Hb : g_Hf;

    int tid  = threadIdx.x;
    int wid  = tid >> 5, lane = tid & 31;
    int u    = cidx * REC_OUT + wid;           // output unit 0..299

    // register-resident recurrent weights: w[g][k] = Wr[v][g*300+u], v = lane+32k
    float w[4][10];
#pragma unroll
    for (int g = 0; g < 4; g++)
#pragma unroll
        for (int k = 0; k < 10; k++) {
            int v = lane + 32 * k;
            w[g][k] = (v < UU) ? Wr[(size_t)v * G4 + g * UU + u] : 0.f;
        }

    // prefetch xp for step s=0
    float xn0 = 0.f, xn1 = 0.f, xn2 = 0.f, xn3 = 0.f;
    if (lane == 0) {
        int t0 = dir ? (T_LEN - 1) : 0;
        const float* xr = xp + (size_t)t0 * G4 + u;
        xn0 = __ldcg(xr);
        xn1 = __ldcg(xr + UU);
        xn2 = __ldcg(xr + 2 * UU);
        xn3 = __ldcg(xr + 3 * UU);
    }

    float c = 0.f;
    for (int s = 0; s < T_LEN; s++) {
        int  t    = dir ? (T_LEN - 1 - s) : s;
        long rrow = dir ? (long)(t + 1) * KP : (long)t * KP;       // h_prev row
        long wrow = dir ? (long)t * KP       : (long)(t + 1) * KP; // h_out row

        // consume prefetched xp, then prefetch step s+1 (a full step of slack)
        float x0 = xn0, x1 = xn1, x2 = xn2, x3 = xn3;
        if (lane == 0 && s + 1 < T_LEN) {
            int tn = dir ? (t - 1) : (t + 1);
            const float* xr = xp + (size_t)tn * G4 + u;
            xn0 = __ldcg(xr);
            xn1 = __ldcg(xr + UU);
            xn2 = __ldcg(xr + 2 * UU);
            xn3 = __ldcg(xr + 3 * UU);
        }

        // poll this warp's 64-float chunk; valid h has bits < 0x40000000
        // (h in [0,1), zeros, pad), poison is 0xFFFFFFFF
        const float4* cp = reinterpret_cast<const float4*>(&Hd[rrow + wid * 64]);
        float4 v;
        bool ok;
        do {
            ok = true;
            if (lane < 16) {
                v = ldcg4(cp + lane);
                ok = (__float_as_uint(v.x) < 0x40000000u) &
                     (__float_as_uint(v.y) < 0x40000000u) &
                     (__float_as_uint(v.z) < 0x40000000u) &
                     (__float_as_uint(v.w) < 0x40000000u);
            }
        } while (!__all_sync(0xffffffffu, ok));

        int p = s & 1;
        if (lane < 16)
            *reinterpret_cast<float4*>(&hbuf[p][wid * 64 + lane * 4]) = v;
        __syncthreads();   // chunks complete; double buffer makes 1 bar/step safe

        // full h row from smem (stride-32: bank-conflict-free)
        float hv[10];
#pragma unroll
        for (int k = 0; k < 10; k++) hv[k] = hbuf[p][lane + 32 * k];

        // four gate dot-products
        float a0 = 0.f, a1 = 0.f, a2 = 0.f, a3 = 0.f;
#pragma unroll
        for (int k = 0; k < 10; k++) {
            a0 = fmaf(hv[k], w[0][k], a0);
            a1 = fmaf(hv[k], w[1][k], a1);
            a2 = fmaf(hv[k], w[2][k], a2);
            a3 = fmaf(hv[k], w[3][k], a3);
        }
#pragma unroll
        for (int off = 16; off > 0; off >>= 1) {
            a0 += __shfl_xor_sync(0xffffffffu, a0, off);
            a1 += __shfl_xor_sync(0xffffffffu, a1, off);
            a2 += __shfl_xor_sync(0xffffffffu, a2, off);
            a3 += __shfl_xor_sync(0xffffffffu, a3, off);
        }

        if (lane == 0) {
            float zi = fsig(x0 + a0);
            float zf = fsig(x1 + a1);
            float zg = fsig(x2 + a2);
            float zo = fsig(x3 + a3);
            c = fmaf(zf, c, zi * zg);
            float h = zo * fsig(c);
            stcg(&Hd[wrow + u], h);
        }
    }
}

// ---------------- T1[t][a] = tanh( sum_u H[t][u] * W1T[u][a] ) --------------
__global__ __launch_bounds__(256) void k_t1() {
    int a0 = blockIdx.x * 64, t0 = blockIdx.y * 64;
    __shared__ float As[20][64];  // H chunk
    __shared__ float Bs[20][64];  // W1T chunk
    int tid = threadIdx.x;
    int tx = tid & 15, ty = tid >> 4;

    float acc[4][4];
#pragma unroll
    for (int i = 0; i < 4; i++)
#pragma unroll
        for (int j = 0; j < 4; j++) acc[i][j] = 0.f;

    for (int k0 = 0; k0 < 600; k0 += 20) {
        for (int i = tid; i < 64 * 20; i += 256) {
            int m = i / 20, kk = i % 20;
            int uu = k0 + kk;
            float v = (uu < UU) ? g_Hf[(size_t)(t0 + m + 1) * KP + uu]
                                : g_Hb[(size_t)(t0 + m) * KP + (uu - UU)];
            As[kk][m] = v;
        }
        for (int i = tid; i < 20 * 64; i += 256) {
            int kk = i / 64, j = i % 64;
            int a = a0 + j;
            Bs[kk][j] = (a < AD) ? g_W1T[(size_t)(k0 + kk) * AD + a] : 0.f;
        }
        __syncthreads();
#pragma unroll
        for (int kk = 0; kk < 20; kk++) {
            float a[4], b[4];
#pragma unroll
            for (int i = 0; i < 4; i++) a[i] = As[kk][ty * 4 + i];
#pragma unroll
            for (int j = 0; j < 4; j++) b[j] = Bs[kk][tx * 4 + j];
#pragma unroll
            for (int i = 0; i < 4; i++)
#pragma unroll
                for (int j = 0; j < 4; j++) acc[i][j] = fmaf(a[i], b[j], acc[i][j]);
        }
        __syncthreads();
    }
#pragma unroll
    for (int i = 0; i < 4; i++)
#pragma unroll
        for (int j = 0; j < 4; j++) {
            int a = a0 + tx * 4 + j;
            if (a < AD)
                g_T1[(size_t)(t0 + ty * 4 + i) * AD + a] = tanhf(acc[i][j]);
        }
}

// ---------------- p[t] = H[t] . dense_w -------------------------------------
__global__ __launch_bounds__(256) void k_p(const float* __restrict__ dw) {
    int wid = threadIdx.x >> 5, lane = threadIdx.x & 31;
    int t = blockIdx.x * 8 + wid;
    if (t >= T_LEN) return;
    float s = 0.f;
    for (int u = lane; u < 600; u += 32) {
        float h = (u < UU) ? g_Hf[(size_t)(t + 1) * KP + u]
                           : g_Hb[(size_t)t * KP + (u - UU)];
        s = fmaf(h, __ldg(&dw[u]), s);
    }
#pragma unroll
    for (int off = 16; off > 0; off >>= 1) s += __shfl_xor_sync(0xffffffffu, s, off);
    if (lane == 0) g_p[t] = s;
}

// ---------------- S2[r][t] = sum_a W2[r][a] * T1[t][a] ----------------------
__global__ __launch_bounds__(256) void k_s2(const float* __restrict__ W2) {
    __shared__ float Ws[RR * AD];   // 42 KB
    int tid = threadIdx.x;
    for (int i = tid; i < RR * AD; i += 256) Ws[i] = W2[i];
    __syncthreads();

    int wid = tid >> 5, lane = tid & 31;
    int t = blockIdx.x * 8 + wid;
    if (t >= T_LEN) return;

    float tv[11];
#pragma unroll
    for (int k = 0; k < 11; k++) {
        int a = lane + 32 * k;
        tv[k] = (a < AD) ? g_T1[(size_t)t * AD + a] : 0.f;
    }
    for (int r = 0; r < RR; r++) {
        float s = 0.f;
#pragma unroll
        for (int k = 0; k < 11; k++) {
            int a = lane + 32 * k;
            if (a < AD) s = fmaf(tv[k], Ws[r * AD + a], s);
        }
#pragma unroll
        for (int off = 16; off > 0; off >>= 1) s += __shfl_xor_sync(0xffffffffu, s, off);
        if (lane == 0) g_S2[(size_t)r * T_LEN + t] = s;
    }
}

// ---------------- softmax over t + weighted p reduction per r ---------------
__global__ __launch_bounds__(256) void k_soft() {
    int r = blockIdx.x;
    int tid = threadIdx.x;
    const float* row = g_S2 + (size_t)r * T_LEN;
    __shared__ float red[256];
    __shared__ float red2[256];

    float m = -1e30f;
    for (int i = tid; i < T_LEN; i += 256) m = fmaxf(m, row[i]);
    red[tid] = m; __syncthreads();
    for (int s = 128; s > 0; s >>= 1) {
        if (tid < s) red[tid] = fmaxf(red[tid], red[tid + s]);
        __syncthreads();
    }
    m = red[0]; __syncthreads();

    float se = 0.f, sp = 0.f;
    for (int i = tid; i < T_LEN; i += 256) {
        float e = expf(row[i] - m);
        se += e;
        sp = fmaf(e, g_p[i], sp);
    }
    red[tid] = se; red2[tid] = sp; __syncthreads();
    for (int s = 128; s > 0; s >>= 1) {
        if (tid < s) { red[tid] += red[tid + s]; red2[tid] += red2[tid + s]; }
        __syncthreads();
    }
    if (tid == 0) g_sr[r] = red2[0] / red[0];
}

// ---------------- final scalar ----------------------------------------------
__global__ void k_fin(const float* __restrict__ db, float* __restrict__ out) {
    int lane = threadIdx.x;
    float s = (lane < RR) ? g_sr[lane] : 0.f;
#pragma unroll
    for (int off = 16; off > 0; off >>= 1) s += __shfl_xor_sync(0xffffffffu, s, off);
    if (lane == 0)
        out[0] = 1.0f / (1.0f + expf(-(s / (float)RR + db[0])));
}

// ---------------- launch ----------------------------------------------------
extern "C" void kernel_launch(void* const* d_in, const int* in_sizes, int n_in,
                              void* d_out, int out_size) {
    const float* emb  = (const float*)d_in[0];
    const float* Wk_f = (const float*)d_in[1];
    const float* Wr_f = (const float*)d_in[2];
    const float* b_f  = (const float*)d_in[3];
    const float* Wk_b = (const float*)d_in[4];
    const float* Wr_b = (const float*)d_in[5];
    const float* b_b  = (const float*)d_in[6];
    const float* W1   = (const float*)d_in[7];
    const float* W2   = (const float*)d_in[8];
    const float* dw   = (const float*)d_in[9];
    const float* db   = (const float*)d_in[10];
    float* out = (float*)d_out;

    // order chosen so k_rec is launch #6 (1-based) / #5 (0-based):
    // ncu -s 5 -c 1 captures k_rec under either convention
    k_xp<<<dim3((G4 + 63) / 64, T_LEN / 64, 2), 256>>>(emb, Wk_f, b_f, Wk_b, b_b);
    k_init<<<2048, 256>>>(W1);
    k_nop<<<1, 32>>>();
    k_nop<<<1, 32>>>();
    k_nop<<<1, 32>>>();
    k_rec<<<2 * REC_NCTA, REC_THREADS>>>(Wr_f, Wr_b);
    k_t1<<<dim3((AD + 63) / 64, T_LEN / 64), 256>>>();
    k_p<<<T_LEN / 8, 256>>>(dw);
    k_s2<<<T_LEN / 8, 256>>>(W2);
    k_soft<<<RR, 256>>>();
    k_fin<<<1, 32>>>(db, out);
}